// round 3
// baseline (speedup 1.0000x reference)
#include <cuda_runtime.h>

#define BATCH 2048
#define IN 256
#define OUT 256
#define OT 16                  // outputs per block
#define BT 16                  // batches per tile
#define BTILES (BATCH / BT)    // 128 batch tiles
#define GRIDX 38               // 38 * 16 = 608 blocks = 4/SM on 152 SMs (one wave)

// Fused persistent kernel:
//  - folds affine: c1 = m*a2*a0, c0 = m*(a2*a1 + a3), held in registers for the
//    block's whole lifetime (one 16-output slice per block)
//  - grid-strides over batch tiles: per tile, stage x in smem, then stream
//    postacts with per-thread STG.128 (evict-first) — the R1 store path that
//    hit 6.1 TB/s; R2's TMA staging regressed and is abandoned.
__global__ __launch_bounds__(256, 4) void kan_fused(const float* __restrict__ x,
                                                    const float4* __restrict__ affine,
                                                    const float* __restrict__ mask,
                                                    float* __restrict__ y,
                                                    float* __restrict__ post) {
    __shared__ float4 xs[BT * (IN / 4)];   // 16 KB x tile

    const int t = threadIdx.x;
    const int o_loc = t >> 4;              // 0..15
    const int lane = t & 15;               // 0..15
    const int o = blockIdx.y * OT + o_loc;

    // ---- fold this thread's 16 (c1, c0) coefficients, once per block ----
    float4 c1r[4], c0r[4];
#pragma unroll
    for (int k = 0; k < 4; k++) {
        const int f = lane + 16 * k;       // float4 index within the row (0..63)
        float4 m4 = reinterpret_cast<const float4*>(mask)[o * (IN / 4) + f];
        const float mm[4] = {m4.x, m4.y, m4.z, m4.w};
        float c1v[4], c0v[4];
#pragma unroll
        for (int j = 0; j < 4; j++) {
            float4 a = affine[o * IN + 4 * f + j];   // (a0,a1,a2,a3)
            c1v[j] = mm[j] * a.z * a.x;
            c0v[j] = mm[j] * fmaf(a.z, a.y, a.w);
        }
        c1r[k] = make_float4(c1v[0], c1v[1], c1v[2], c1v[3]);
        c0r[k] = make_float4(c0v[0], c0v[1], c0v[2], c0v[3]);
    }

    // ---- persistent loop over batch tiles ----
    for (int bx = blockIdx.x; bx < BTILES; bx += GRIDX) {
        const int b0 = bx * BT;

        __syncthreads();   // previous tile's readers done before xs overwrite
        const float4* xg = reinterpret_cast<const float4*>(x + (size_t)b0 * IN);
#pragma unroll
        for (int j = 0; j < 4; j++) xs[t + 256 * j] = xg[t + 256 * j];
        __syncthreads();

#pragma unroll 4
        for (int bl = 0; bl < BT; bl++) {
            const int b = b0 + bl;
            float4* prow = reinterpret_cast<float4*>(post + ((size_t)b * OUT + o) * IN);
            float acc = 0.0f;
#pragma unroll
            for (int k = 0; k < 4; k++) {
                float4 xv = xs[bl * (IN / 4) + lane + 16 * k];
                float4 p;
                p.x = fmaf(c1r[k].x, xv.x, c0r[k].x);
                p.y = fmaf(c1r[k].y, xv.y, c0r[k].y);
                p.z = fmaf(c1r[k].z, xv.z, c0r[k].z);
                p.w = fmaf(c1r[k].w, xv.w, c0r[k].w);
                acc += (p.x + p.y) + (p.z + p.w);
                // 16 lanes, consecutive f -> contiguous 256B runs, evict-first
                __stcs(&prow[lane + 16 * k], p);
            }
            // reduce across the 16 lanes sharing this output
#pragma unroll
            for (int off = 8; off; off >>= 1)
                acc += __shfl_xor_sync(0xffffffffu, acc, off);
            if (lane == 0) y[(size_t)b * OUT + o] = acc;
        }
    }
}

extern "C" void kernel_launch(void* const* d_in, const int* in_sizes, int n_in,
                              void* d_out, int out_size) {
    const float*  x      = (const float*)d_in[0];   // [2048, 256]
    const float4* affine = (const float4*)d_in[1];  // [256, 256, 4]
    const float*  mask   = (const float*)d_in[2];   // [256, 256]

    float* y    = (float*)d_out;                        // [2048, 256]
    float* post = (float*)d_out + (size_t)BATCH * OUT;  // [2048, 256, 256]

    dim3 grid(GRIDX, OUT / OT);   // 608 blocks, persistent over 128 batch tiles
    kan_fused<<<grid, 256>>>(x, affine, mask, y, post);
}

// round 4
// speedup vs baseline: 1.2255x; 1.2255x over previous
#include <cuda_runtime.h>

#define BATCH 2048
#define IN 256
#define OUT 256
#define OT 16   // outputs per block
#define BT 8    // batches per block (halved vs R1 to cut wave-quantization tail)

// Folded affine coefficients: postact = c1*x + c0
__device__ float g_c1[OUT * IN];
__device__ float g_c0[OUT * IN];

__global__ __launch_bounds__(256) void kan_precompute(const float* __restrict__ affine,
                                                      const float* __restrict__ mask) {
    int idx = blockIdx.x * blockDim.x + threadIdx.x;  // 0 .. OUT*IN-1
    float4 a = reinterpret_cast<const float4*>(affine)[idx];  // (a0,a1,a2,a3)
    float m = mask[idx];
    g_c1[idx] = m * a.z * a.x;
    g_c0[idx] = m * fmaf(a.z, a.y, a.w);
}

__global__ __launch_bounds__(256) void kan_main(const float* __restrict__ x,
                                                float* __restrict__ y,
                                                float* __restrict__ post) {
    __shared__ float4 xs[BT * (IN / 4)];  // 8 batches x 64 float4 = 8 KB

    const int t = threadIdx.x;
    const int o_loc = t >> 4;      // 0..15
    const int lane = t & 15;       // 0..15
    const int o = blockIdx.y * OT + o_loc;
    const int b0 = blockIdx.x * BT;

    // This thread's 16-coefficient slice, reused for all BT batches.
    float4 c1r[4], c0r[4];
#pragma unroll
    for (int k = 0; k < 4; k++) {
        int f = lane + 16 * k;
        c1r[k] = reinterpret_cast<const float4*>(g_c1)[o * (IN / 4) + f];
        c0r[k] = reinterpret_cast<const float4*>(g_c0)[o * (IN / 4) + f];
    }

    // Cooperative load of the x tile (BT*IN/4 = 512 float4s, 2 per thread).
    const float4* xg = reinterpret_cast<const float4*>(x + (size_t)b0 * IN);
#pragma unroll
    for (int j = 0; j < BT * (IN / 4) / 256; j++) xs[t + 256 * j] = xg[t + 256 * j];
    __syncthreads();

#pragma unroll 4
    for (int bl = 0; bl < BT; bl++) {
        const int b = b0 + bl;
        float4* prow = reinterpret_cast<float4*>(post + ((size_t)b * OUT + o) * IN);
        float acc = 0.0f;
#pragma unroll
        for (int k = 0; k < 4; k++) {
            float4 xv = xs[bl * (IN / 4) + lane + 16 * k];
            float4 p;
            p.x = fmaf(c1r[k].x, xv.x, c0r[k].x);
            p.y = fmaf(c1r[k].y, xv.y, c0r[k].y);
            p.z = fmaf(c1r[k].z, xv.z, c0r[k].z);
            p.w = fmaf(c1r[k].w, xv.w, c0r[k].w);
            acc += (p.x + p.y) + (p.z + p.w);
            // 16 lanes with consecutive f -> contiguous 256B run, evict-first.
            __stcs(&prow[lane + 16 * k], p);
        }
#pragma unroll
        for (int off = 8; off; off >>= 1)
            acc += __shfl_xor_sync(0xffffffffu, acc, off);
        if (lane == 0) y[(size_t)b * OUT + o] = acc;
    }
}

extern "C" void kernel_launch(void* const* d_in, const int* in_sizes, int n_in,
                              void* d_out, int out_size) {
    const float* x      = (const float*)d_in[0];  // [2048, 256]
    const float* affine = (const float*)d_in[1];  // [256, 256, 4]
    const float* mask   = (const float*)d_in[2];  // [256, 256]

    float* y    = (float*)d_out;                        // [2048, 256]
    float* post = (float*)d_out + (size_t)BATCH * OUT;  // [2048, 256, 256]

    kan_precompute<<<(OUT * IN) / 256, 256>>>(affine, mask);

    dim3 grid(BATCH / BT, OUT / OT);   // (256, 16) = 4096 blocks
    kan_main<<<grid, 256>>>(x, y, post);
}